// round 4
// baseline (speedup 1.0000x reference)
#include <cuda_runtime.h>
#include <cuda_bf16.h>
#include <cuda_fp8.h>
#include <cstdint>
#include <math.h>

// Problem constants: B=4096, IN_F=2048, OUT_F=8192, NG=16
#define M_DIM   4096
#define K_DIM   2048
#define N_DIM   8192
#define NGROUPS 16
#define GSIZE   (N_DIM / NGROUPS)   // 512
#define EPS     1e-5f

// GEMM tiling: CTA 128x256, 8 warps of 64x64
#define BM 128
#define BN 256
#define CHUNK 64                    // K elems per chunk = 128 B rows (bf16) / 128 fp8
#define NCHUNK 32
#define A_ST (BM * 128)             // 16 KB
#define B_ST (BN * 128)             // 32 KB
#define STG  (A_ST + B_ST)          // 48 KB
#define NSTAGE 4
#define SMEM_GEMM (NSTAGE * STG)    // 196608

#define CORR_INV (1.0f / 16384.0f)  // 2^-14 combined fp8 scale

#define SWZ(o) ((o) ^ ((((uint32_t)(o)) >> 3) & 0x70))

// -------- scratch --------------------------------------------------------
__device__ __nv_bfloat16 g_xh[(size_t)M_DIM * K_DIM];     // 16 MB
__device__ __nv_bfloat16 g_wh[(size_t)N_DIM * K_DIM];     // 32 MB
// fp8 concat layout: row r, chunk c: bytes [r*4096 + c*128 .. +127]
//   A: [Ah8(64B) | Al8*2^9(64B)]      B: [Bl8*2^14(64B) | Bh8*2^5(64B)]
__device__ uint8_t g_a8[(size_t)M_DIM * 2 * K_DIM];       // 16 MB
__device__ uint8_t g_b8[(size_t)N_DIM * 2 * K_DIM];       // 32 MB

// -------- PTX helpers (all plain sm_80/sm_89 PTX) ------------------------
__device__ __forceinline__ uint32_t smem_u32(const void* p) {
    uint32_t a;
    asm("{ .reg .u64 t; cvta.to.shared.u64 t, %1; cvt.u32.u64 %0, t; }" : "=r"(a) : "l"(p));
    return a;
}
#define CP_ASYNC16(dst, src) \
    asm volatile("cp.async.cg.shared.global [%0], [%1], 16;" :: "r"(dst), "l"(src) : "memory")
#define CP_COMMIT() asm volatile("cp.async.commit_group;" ::: "memory")
#define CP_WAIT(n)  asm volatile("cp.async.wait_group %0;" :: "n"(n) : "memory")

#define LDSM_X4(r0, r1, r2, r3, addr) \
    asm volatile("ldmatrix.sync.aligned.m8n8.x4.shared.b16 {%0,%1,%2,%3}, [%4];" \
        : "=r"(r0), "=r"(r1), "=r"(r2), "=r"(r3) : "r"(addr))

#define MMA16816(d, a, b0v, b1v) \
    asm volatile("mma.sync.aligned.m16n8k16.row.col.f32.bf16.bf16.f32 " \
        "{%0,%1,%2,%3}, {%4,%5,%6,%7}, {%8,%9}, {%0,%1,%2,%3};" \
        : "+f"((d)[0]), "+f"((d)[1]), "+f"((d)[2]), "+f"((d)[3]) \
        : "r"((a)[0]), "r"((a)[1]), "r"((a)[2]), "r"((a)[3]), "r"(b0v), "r"(b1v))

#define QMMA16832(d, a, b0v, b1v) \
    asm volatile("mma.sync.aligned.m16n8k32.row.col.f32.e4m3.e4m3.f32 " \
        "{%0,%1,%2,%3}, {%4,%5,%6,%7}, {%8,%9}, {%0,%1,%2,%3};" \
        : "+f"((d)[0]), "+f"((d)[1]), "+f"((d)[2]), "+f"((d)[3]) \
        : "r"((a)[0]), "r"((a)[1]), "r"((a)[2]), "r"((a)[3]), "r"(b0v), "r"(b1v))

// -------- split: fp32 -> bf16 hi + packed fp8 (hi, lo*scale) -------------
// hiScale/loScale: x -> (1, 512); W -> (32, 16384). hiHigh: which 64B half
// of the 128B chunk row holds the hi part (A: hi in low half; B: hi in high).
__global__ __launch_bounds__(256)
void split_kernel(const float* __restrict__ src,
                  __nv_bfloat16* __restrict__ hi,
                  uint8_t* __restrict__ q8,
                  int n8, float hiScale, float loScale, int hiHigh)
{
    int i = blockIdx.x * 256 + threadIdx.x;
    if (i >= n8) return;
    const float4 v0 = reinterpret_cast<const float4*>(src)[i * 2];
    const float4 v1 = reinterpret_cast<const float4*>(src)[i * 2 + 1];
    float v[8] = {v0.x, v0.y, v0.z, v0.w, v1.x, v1.y, v1.z, v1.w};

    float hf[8], lf[8];
    uint32_t hp[4];
#pragma unroll
    for (int j = 0; j < 4; j++) {
        __nv_bfloat16 h0 = __float2bfloat16(v[2 * j]);
        __nv_bfloat16 h1 = __float2bfloat16(v[2 * j + 1]);
        hf[2 * j]     = __bfloat162float(h0);
        hf[2 * j + 1] = __bfloat162float(h1);
        lf[2 * j]     = v[2 * j]     - hf[2 * j];
        lf[2 * j + 1] = v[2 * j + 1] - hf[2 * j + 1];
        hp[j] = (uint32_t)__bfloat16_as_ushort(h0) |
                ((uint32_t)__bfloat16_as_ushort(h1) << 16);
    }
    // bf16 hi: 16 B
    uint4 uh = {hp[0], hp[1], hp[2], hp[3]};
    reinterpret_cast<uint4*>(hi)[i] = uh;

    // fp8 hi / lo: 8 B each
    uint32_t h8[2], l8[2];
#pragma unroll
    for (int j = 0; j < 2; j++) {
        __nv_fp8x2_storage_t a = __nv_cvt_float2_to_fp8x2(
            make_float2(hf[4*j+0]*hiScale, hf[4*j+1]*hiScale), __NV_SATFINITE, __NV_E4M3);
        __nv_fp8x2_storage_t b = __nv_cvt_float2_to_fp8x2(
            make_float2(hf[4*j+2]*hiScale, hf[4*j+3]*hiScale), __NV_SATFINITE, __NV_E4M3);
        h8[j] = (uint32_t)a | ((uint32_t)b << 16);
        __nv_fp8x2_storage_t c = __nv_cvt_float2_to_fp8x2(
            make_float2(lf[4*j+0]*loScale, lf[4*j+1]*loScale), __NV_SATFINITE, __NV_E4M3);
        __nv_fp8x2_storage_t d = __nv_cvt_float2_to_fp8x2(
            make_float2(lf[4*j+2]*loScale, lf[4*j+3]*loScale), __NV_SATFINITE, __NV_E4M3);
        l8[j] = (uint32_t)c | ((uint32_t)d << 16);
    }
    const size_t k0 = (size_t)i * 8;
    const size_t m  = k0 >> 11;            // / K_DIM
    const int kk    = (int)(k0 & 2047);
    const int cidx  = kk >> 6;
    const int off   = kk & 63;
    uint8_t* base = q8 + m * 4096 + cidx * 128;
    uint2 uh8 = {h8[0], h8[1]}, ul8 = {l8[0], l8[1]};
    *reinterpret_cast<uint2*>(base + hiHigh * 64 + off)       = uh8;
    *reinterpret_cast<uint2*>(base + (1 - hiHigh) * 64 + off) = ul8;
}

// -------- main GEMM: C = Ah(bf16) @ Bh(bf16)^T + bias --------------------
__global__ __launch_bounds__(256, 1)
void gemm_main_kernel(const float* __restrict__ bias, float* __restrict__ C)
{
    extern __shared__ __align__(128) char sm[];
    const uint32_t smem_base = smem_u32(sm);
    const int tid = threadIdx.x, wid = tid >> 5, lane = tid & 31;
    const int wm = wid & 1, wn = wid >> 1;          // 2 x 4 warps, 64x64 each
    const int mrow0 = blockIdx.x * BM;
    const int nrow0 = blockIdx.y * BN;

    float acc[4][8][4];
#pragma unroll
    for (int i = 0; i < 4; i++)
#pragma unroll
        for (int j = 0; j < 8; j++)
#pragma unroll
            for (int r = 0; r < 4; r++) acc[i][j][r] = 0.0f;

    auto prefetch = [&](int c) {
        const uint32_t base = smem_base + (c & 3) * STG;
        const int k0 = c * CHUNK;
#pragma unroll
        for (int i = 0; i < 4; i++) {
            int idx = tid + i * 256; int r = idx >> 3, u = idx & 7;
            CP_ASYNC16(base + SWZ(r * 128 + u * 16),
                       &g_xh[(size_t)(mrow0 + r) * K_DIM + k0 + u * 8]);
        }
#pragma unroll
        for (int i = 0; i < 8; i++) {
            int idx = tid + i * 256; int r = idx >> 3, u = idx & 7;
            CP_ASYNC16(base + A_ST + SWZ(r * 128 + u * 16),
                       &g_wh[(size_t)(nrow0 + r) * K_DIM + k0 + u * 8]);
        }
    };

    prefetch(0); CP_COMMIT();
    prefetch(1); CP_COMMIT();

    const int a_row = wm * 64 + (lane & 15);
    const int a_kb  = (lane >> 4) * 16;
    const int b_row = wn * 64 + (lane & 7) + ((lane >> 4) << 3);
    const int b_kb  = ((lane >> 3) & 1) * 16;

    for (int c = 0; c < NCHUNK; ++c) {
        if (c + 2 < NCHUNK) prefetch(c + 2);
        CP_COMMIT();
        CP_WAIT(2);
        __syncthreads();

        const uint32_t aB = smem_base + (c & 3) * STG;
        const uint32_t bB = aB + A_ST;
#pragma unroll
        for (int ks = 0; ks < 4; ++ks) {
            uint32_t a[4][4], b[4][4];
#pragma unroll
            for (int i = 0; i < 4; i++)
                LDSM_X4(a[i][0], a[i][1], a[i][2], a[i][3],
                        aB + SWZ((a_row + i * 16) * 128 + ks * 32 + a_kb));
#pragma unroll
            for (int j = 0; j < 4; j++)
                LDSM_X4(b[j][0], b[j][1], b[j][2], b[j][3],
                        bB + SWZ((b_row + j * 16) * 128 + ks * 32 + b_kb));
#pragma unroll
            for (int i = 0; i < 4; i++)
#pragma unroll
                for (int j = 0; j < 4; j++) {
                    MMA16816(acc[i][2 * j + 0], a[i], b[j][0], b[j][1]);
                    MMA16816(acc[i][2 * j + 1], a[i], b[j][2], b[j][3]);
                }
        }
    }

    const int m_base = mrow0 + wm * 64 + (lane >> 2);
    const int n_base = nrow0 + wn * 64 + (lane & 3) * 2;
#pragma unroll
    for (int i = 0; i < 4; i++) {
#pragma unroll
        for (int j = 0; j < 8; j++) {
            int n0 = n_base + j * 8;
            float b0 = bias[n0], b1 = bias[n0 + 1];
            int m0 = m_base + i * 16;
            float2 lo2 = {acc[i][j][0] + b0, acc[i][j][1] + b1};
            float2 hi2 = {acc[i][j][2] + b0, acc[i][j][3] + b1};
            *reinterpret_cast<float2*>(C + (size_t)m0 * N_DIM + n0)       = lo2;
            *reinterpret_cast<float2*>(C + (size_t)(m0 + 8) * N_DIM + n0) = hi2;
        }
    }
}

// -------- correction GEMM: C += (A8 @ B8^T) * 2^-14 (fp8 e4m3, K=4096) ---
__global__ __launch_bounds__(256, 1)
void gemm_corr_kernel(float* __restrict__ C)
{
    extern __shared__ __align__(128) char sm[];
    const uint32_t smem_base = smem_u32(sm);
    const int tid = threadIdx.x, wid = tid >> 5, lane = tid & 31;
    const int wm = wid & 1, wn = wid >> 1;
    const int mrow0 = blockIdx.x * BM;
    const int nrow0 = blockIdx.y * BN;

    float acc[4][8][4];
#pragma unroll
    for (int i = 0; i < 4; i++)
#pragma unroll
        for (int j = 0; j < 8; j++)
#pragma unroll
            for (int r = 0; r < 4; r++) acc[i][j][r] = 0.0f;

    auto prefetch = [&](int c) {
        const uint32_t base = smem_base + (c & 3) * STG;
#pragma unroll
        for (int i = 0; i < 4; i++) {
            int idx = tid + i * 256; int r = idx >> 3, u = idx & 7;
            CP_ASYNC16(base + SWZ(r * 128 + u * 16),
                       g_a8 + (size_t)(mrow0 + r) * 4096 + c * 128 + u * 16);
        }
#pragma unroll
        for (int i = 0; i < 8; i++) {
            int idx = tid + i * 256; int r = idx >> 3, u = idx & 7;
            CP_ASYNC16(base + A_ST + SWZ(r * 128 + u * 16),
                       g_b8 + (size_t)(nrow0 + r) * 4096 + c * 128 + u * 16);
        }
    };

    prefetch(0); CP_COMMIT();
    prefetch(1); CP_COMMIT();

    const int a_row = wm * 64 + (lane & 15);
    const int a_kb  = (lane >> 4) * 16;
    const int b_row = wn * 64 + (lane & 7) + ((lane >> 4) << 3);
    const int b_kb  = ((lane >> 3) & 1) * 16;

    for (int c = 0; c < NCHUNK; ++c) {
        if (c + 2 < NCHUNK) prefetch(c + 2);
        CP_COMMIT();
        CP_WAIT(2);
        __syncthreads();

        const uint32_t aB = smem_base + (c & 3) * STG;
        const uint32_t bB = aB + A_ST;
#pragma unroll
        for (int ks = 0; ks < 4; ++ks) {             // each ks = k32 fp8
            uint32_t a[4][4], b[4][4];
#pragma unroll
            for (int i = 0; i < 4; i++)
                LDSM_X4(a[i][0], a[i][1], a[i][2], a[i][3],
                        aB + SWZ((a_row + i * 16) * 128 + ks * 32 + a_kb));
#pragma unroll
            for (int j = 0; j < 4; j++)
                LDSM_X4(b[j][0], b[j][1], b[j][2], b[j][3],
                        bB + SWZ((b_row + j * 16) * 128 + ks * 32 + b_kb));
#pragma unroll
            for (int i = 0; i < 4; i++)
#pragma unroll
                for (int j = 0; j < 4; j++) {
                    QMMA16832(acc[i][2 * j + 0], a[i], b[j][0], b[j][1]);
                    QMMA16832(acc[i][2 * j + 1], a[i], b[j][2], b[j][3]);
                }
        }
    }

    const int m_base = mrow0 + wm * 64 + (lane >> 2);
    const int n_base = nrow0 + wn * 64 + (lane & 3) * 2;
#pragma unroll
    for (int i = 0; i < 4; i++) {
#pragma unroll
        for (int j = 0; j < 8; j++) {
            int n0 = n_base + j * 8;
            int m0 = m_base + i * 16;
            float2* p0 = reinterpret_cast<float2*>(C + (size_t)m0 * N_DIM + n0);
            float2* p1 = reinterpret_cast<float2*>(C + (size_t)(m0 + 8) * N_DIM + n0);
            float2 v0 = *p0, v1 = *p1;
            v0.x += acc[i][j][0] * CORR_INV;  v0.y += acc[i][j][1] * CORR_INV;
            v1.x += acc[i][j][2] * CORR_INV;  v1.y += acc[i][j][3] * CORR_INV;
            *p0 = v0;  *p1 = v1;
        }
    }
}

// -------- GroupNorm + SiLU + mult + SiLU (warp per group, in place) ------
__device__ __forceinline__ float sigmoidf_(float x) { return 1.0f / (1.0f + expf(-x)); }

__global__ __launch_bounds__(512)
void gn_silu_kernel(float* __restrict__ y,
                    const float* __restrict__ gn_w,
                    const float* __restrict__ gn_b,
                    const float* __restrict__ mult_w)
{
    const int row = blockIdx.x;
    const int w   = threadIdx.x >> 5;     // group 0..15
    const int lane = threadIdx.x & 31;

    float4* p = reinterpret_cast<float4*>(y + (size_t)row * N_DIM + w * GSIZE);
    float4 v[4];
#pragma unroll
    for (int t = 0; t < 4; t++) v[t] = p[lane + t * 32];

    float s = 0.0f, ss = 0.0f;
#pragma unroll
    for (int t = 0; t < 4; t++) {
        s  += v[t].x + v[t].y + v[t].z + v[t].w;
        ss += v[t].x*v[t].x + v[t].y*v[t].y + v[t].z*v[t].z + v[t].w*v[t].w;
    }
#pragma unroll
    for (int o = 16; o > 0; o >>= 1) {
        s  += __shfl_xor_sync(0xffffffffu, s,  o);
        ss += __shfl_xor_sync(0xffffffffu, ss, o);
    }
    const float inv_n = 1.0f / (float)GSIZE;
    const float mean  = s * inv_n;
    const float var   = fmaxf(ss * inv_n - mean * mean, 0.0f);
    const float rstd  = rsqrtf(var + EPS);

#pragma unroll
    for (int t = 0; t < 4; t++) {
        float vv[4] = {v[t].x, v[t].y, v[t].z, v[t].w};
        float out[4];
        const int c0 = w * GSIZE + (lane + t * 32) * 4;
#pragma unroll
        for (int j = 0; j < 4; j++) {
            int c = c0 + j;
            float n  = (vv[j] - mean) * rstd * gn_w[c] + gn_b[c];
            float s1 = n * sigmoidf_(n);
            float m  = s1 * mult_w[c];
            out[j]   = m * sigmoidf_(m);
        }
        float4 o = {out[0], out[1], out[2], out[3]};
        p[lane + t * 32] = o;
    }
}

// -------------------------------------------------------------------------
extern "C" void kernel_launch(void* const* d_in, const int* in_sizes, int n_in,
                              void* d_out, int out_size)
{
    const float* x      = (const float*)d_in[0];
    const float* W      = (const float*)d_in[1];
    const float* b      = (const float*)d_in[2];
    const float* gn_w   = (const float*)d_in[3];
    const float* gn_b   = (const float*)d_in[4];
    const float* mult_w = (const float*)d_in[5];
    float* out = (float*)d_out;

    __nv_bfloat16 *xh, *wh;
    uint8_t *a8, *b8;
    cudaGetSymbolAddress((void**)&xh, g_xh);
    cudaGetSymbolAddress((void**)&wh, g_wh);
    cudaGetSymbolAddress((void**)&a8, g_a8);
    cudaGetSymbolAddress((void**)&b8, g_b8);

    // splits: x -> (hi scale 1, lo scale 2^9, hi in LOW half)
    //         W -> (hi scale 2^5, lo scale 2^14, hi in HIGH half)
    int n8x = (M_DIM * K_DIM) / 8;
    int n8w = (N_DIM * K_DIM) / 8;
    split_kernel<<<(n8x + 255) / 256, 256>>>(x, xh, a8, n8x, 1.0f, 512.0f, 0);
    split_kernel<<<(n8w + 255) / 256, 256>>>(W, wh, b8, n8w, 32.0f, 16384.0f, 1);

    cudaFuncSetAttribute(gemm_main_kernel,
                         cudaFuncAttributeMaxDynamicSharedMemorySize, SMEM_GEMM);
    cudaFuncSetAttribute(gemm_corr_kernel,
                         cudaFuncAttributeMaxDynamicSharedMemorySize, SMEM_GEMM);

    dim3 ggrid(M_DIM / BM, N_DIM / BN);   // (32, 32)
    gemm_main_kernel<<<ggrid, 256, SMEM_GEMM>>>(b, out);
    gemm_corr_kernel<<<ggrid, 256, SMEM_GEMM>>>(out);

    gn_silu_kernel<<<M_DIM, 512>>>(out, gn_w, gn_b, mult_w);
}

// round 5
// speedup vs baseline: 1.6098x; 1.6098x over previous
#include <cuda_runtime.h>
#include <cuda_bf16.h>
#include <cuda_fp8.h>
#include <cstdint>
#include <math.h>

// Problem constants: B=4096, IN_F=2048, OUT_F=8192, NG=16
#define M_DIM   4096
#define K_DIM   2048
#define N_DIM   8192
#define NGROUPS 16
#define GSIZE   (N_DIM / NGROUPS)   // 512
#define EPS     1e-5f

// GEMM tiling: CTA 128x128, 8 warps of 32x64 (4M x 2N)
#define BM 128
#define BN 128
#define CHUNK 64                    // K elems per chunk = 128 B rows (bf16) / 128 fp8
#define NCHUNK 32
#define A_ST (BM * 128)             // 16 KB
#define B_ST (BN * 128)             // 16 KB
#define STG  (A_ST + B_ST)          // 32 KB
#define NSTAGE 3
#define SMEM_GEMM (NSTAGE * STG)    // 98304 -> 2 CTAs/SM

#define CORR_INV (1.0f / 16384.0f)  // 2^-14 combined fp8 scale

#define SWZ(o) ((o) ^ ((((uint32_t)(o)) >> 3) & 0x70))

// -------- scratch --------------------------------------------------------
__device__ __nv_bfloat16 g_xh[(size_t)M_DIM * K_DIM];     // 16 MB
__device__ __nv_bfloat16 g_wh[(size_t)N_DIM * K_DIM];     // 32 MB
// fp8 concat layout: row r, chunk c: bytes [r*4096 + c*128 .. +127]
//   A: [Ah8(64B) | Al8*2^9(64B)]      B: [Bl8*2^14(64B) | Bh8*2^5(64B)]
__device__ uint8_t g_a8[(size_t)M_DIM * 2 * K_DIM];       // 16 MB
__device__ uint8_t g_b8[(size_t)N_DIM * 2 * K_DIM];       // 32 MB

// -------- PTX helpers (plain sm_80/sm_89 PTX) ----------------------------
__device__ __forceinline__ uint32_t smem_u32(const void* p) {
    uint32_t a;
    asm("{ .reg .u64 t; cvta.to.shared.u64 t, %1; cvt.u32.u64 %0, t; }" : "=r"(a) : "l"(p));
    return a;
}
#define CP_ASYNC16(dst, src) \
    asm volatile("cp.async.cg.shared.global [%0], [%1], 16;" :: "r"(dst), "l"(src) : "memory")
#define CP_COMMIT() asm volatile("cp.async.commit_group;" ::: "memory")
#define CP_WAIT(n)  asm volatile("cp.async.wait_group %0;" :: "n"(n) : "memory")

#define LDSM_X4(r0, r1, r2, r3, addr) \
    asm volatile("ldmatrix.sync.aligned.m8n8.x4.shared.b16 {%0,%1,%2,%3}, [%4];" \
        : "=r"(r0), "=r"(r1), "=r"(r2), "=r"(r3) : "r"(addr))

#define MMA16816(d, a, b0v, b1v) \
    asm volatile("mma.sync.aligned.m16n8k16.row.col.f32.bf16.bf16.f32 " \
        "{%0,%1,%2,%3}, {%4,%5,%6,%7}, {%8,%9}, {%0,%1,%2,%3};" \
        : "+f"((d)[0]), "+f"((d)[1]), "+f"((d)[2]), "+f"((d)[3]) \
        : "r"((a)[0]), "r"((a)[1]), "r"((a)[2]), "r"((a)[3]), "r"(b0v), "r"(b1v))

#define QMMA16832(d, a, b0v, b1v) \
    asm volatile("mma.sync.aligned.m16n8k32.row.col.f32.e4m3.e4m3.f32 " \
        "{%0,%1,%2,%3}, {%4,%5,%6,%7}, {%8,%9}, {%0,%1,%2,%3};" \
        : "+f"((d)[0]), "+f"((d)[1]), "+f"((d)[2]), "+f"((d)[3]) \
        : "r"((a)[0]), "r"((a)[1]), "r"((a)[2]), "r"((a)[3]), "r"(b0v), "r"(b1v))

// -------- split: fp32 -> bf16 hi + packed fp8 (hi, lo*scale) -------------
// x -> (hiScale 1, loScale 2^9, hi in LOW half); W -> (2^5, 2^14, hi HIGH).
__global__ __launch_bounds__(256)
void split_kernel(const float* __restrict__ src,
                  __nv_bfloat16* __restrict__ hi,
                  uint8_t* __restrict__ q8,
                  int n8, float hiScale, float loScale, int hiHigh)
{
    int i = blockIdx.x * 256 + threadIdx.x;
    if (i >= n8) return;
    const float4 v0 = reinterpret_cast<const float4*>(src)[i * 2];
    const float4 v1 = reinterpret_cast<const float4*>(src)[i * 2 + 1];
    float v[8] = {v0.x, v0.y, v0.z, v0.w, v1.x, v1.y, v1.z, v1.w};

    float hf[8], lf[8];
    uint32_t hp[4];
#pragma unroll
    for (int j = 0; j < 4; j++) {
        __nv_bfloat16 h0 = __float2bfloat16(v[2 * j]);
        __nv_bfloat16 h1 = __float2bfloat16(v[2 * j + 1]);
        hf[2 * j]     = __bfloat162float(h0);
        hf[2 * j + 1] = __bfloat162float(h1);
        lf[2 * j]     = v[2 * j]     - hf[2 * j];
        lf[2 * j + 1] = v[2 * j + 1] - hf[2 * j + 1];
        hp[j] = (uint32_t)__bfloat16_as_ushort(h0) |
                ((uint32_t)__bfloat16_as_ushort(h1) << 16);
    }
    uint4 uh = {hp[0], hp[1], hp[2], hp[3]};
    reinterpret_cast<uint4*>(hi)[i] = uh;

    uint32_t h8[2], l8[2];
#pragma unroll
    for (int j = 0; j < 2; j++) {
        __nv_fp8x2_storage_t a = __nv_cvt_float2_to_fp8x2(
            make_float2(hf[4*j+0]*hiScale, hf[4*j+1]*hiScale), __NV_SATFINITE, __NV_E4M3);
        __nv_fp8x2_storage_t b = __nv_cvt_float2_to_fp8x2(
            make_float2(hf[4*j+2]*hiScale, hf[4*j+3]*hiScale), __NV_SATFINITE, __NV_E4M3);
        h8[j] = (uint32_t)a | ((uint32_t)b << 16);
        __nv_fp8x2_storage_t c = __nv_cvt_float2_to_fp8x2(
            make_float2(lf[4*j+0]*loScale, lf[4*j+1]*loScale), __NV_SATFINITE, __NV_E4M3);
        __nv_fp8x2_storage_t d = __nv_cvt_float2_to_fp8x2(
            make_float2(lf[4*j+2]*loScale, lf[4*j+3]*loScale), __NV_SATFINITE, __NV_E4M3);
        l8[j] = (uint32_t)c | ((uint32_t)d << 16);
    }
    const size_t k0 = (size_t)i * 8;
    const size_t m  = k0 >> 11;
    const int kk    = (int)(k0 & 2047);
    const int cidx  = kk >> 6;
    const int off   = kk & 63;
    uint8_t* base = q8 + m * 4096 + cidx * 128;
    uint2 uh8 = {h8[0], h8[1]}, ul8 = {l8[0], l8[1]};
    *reinterpret_cast<uint2*>(base + hiHigh * 64 + off)       = uh8;
    *reinterpret_cast<uint2*>(base + (1 - hiHigh) * 64 + off) = ul8;
}

// -------- main GEMM: C = Ah(bf16) @ Bh(bf16)^T + bias --------------------
__global__ __launch_bounds__(256, 2)
void gemm_main_kernel(const float* __restrict__ bias, float* __restrict__ C)
{
    extern __shared__ __align__(128) char sm[];
    const uint32_t smem_base = smem_u32(sm);
    const int tid = threadIdx.x, wid = tid >> 5, lane = tid & 31;
    const int wm = wid & 3, wn = wid >> 2;           // 4M x 2N warps, 32x64 each
    const int mrow0 = blockIdx.x * BM;
    const int nrow0 = blockIdx.y * BN;

    float acc[2][8][4];
#pragma unroll
    for (int i = 0; i < 2; i++)
#pragma unroll
        for (int j = 0; j < 8; j++)
#pragma unroll
            for (int r = 0; r < 4; r++) acc[i][j][r] = 0.0f;

    auto prefetch = [&](int c) {
        const uint32_t base = smem_base + (c % NSTAGE) * STG;
        const int k0 = c * CHUNK;
#pragma unroll
        for (int i = 0; i < 4; i++) {
            int idx = tid + i * 256; int r = idx >> 3, u = idx & 7;
            CP_ASYNC16(base + SWZ(r * 128 + u * 16),
                       &g_xh[(size_t)(mrow0 + r) * K_DIM + k0 + u * 8]);
        }
#pragma unroll
        for (int i = 0; i < 4; i++) {
            int idx = tid + i * 256; int r = idx >> 3, u = idx & 7;
            CP_ASYNC16(base + A_ST + SWZ(r * 128 + u * 16),
                       &g_wh[(size_t)(nrow0 + r) * K_DIM + k0 + u * 8]);
        }
    };

    prefetch(0); CP_COMMIT();
    prefetch(1); CP_COMMIT();

    const int a_row = wm * 32 + (lane & 15);
    const int a_kb  = (lane >> 4) * 16;
    const int b_row = wn * 64 + (lane & 7) + ((lane >> 4) << 3);
    const int b_kb  = ((lane >> 3) & 1) * 16;

    for (int c = 0; c < NCHUNK; ++c) {
        if (c + 2 < NCHUNK) prefetch(c + 2);
        CP_COMMIT();
        CP_WAIT(2);
        __syncthreads();

        const uint32_t aB = smem_base + (c % NSTAGE) * STG;
        const uint32_t bB = aB + A_ST;
#pragma unroll
        for (int ks = 0; ks < 4; ++ks) {
            uint32_t a[2][4], b[4][4];
#pragma unroll
            for (int i = 0; i < 2; i++)
                LDSM_X4(a[i][0], a[i][1], a[i][2], a[i][3],
                        aB + SWZ((a_row + i * 16) * 128 + ks * 32 + a_kb));
#pragma unroll
            for (int j = 0; j < 4; j++)
                LDSM_X4(b[j][0], b[j][1], b[j][2], b[j][3],
                        bB + SWZ((b_row + j * 16) * 128 + ks * 32 + b_kb));
#pragma unroll
            for (int i = 0; i < 2; i++)
#pragma unroll
                for (int j = 0; j < 4; j++) {
                    MMA16816(acc[i][2 * j + 0], a[i], b[j][0], b[j][1]);
                    MMA16816(acc[i][2 * j + 1], a[i], b[j][2], b[j][3]);
                }
        }
        __syncthreads();
    }

    const int m_base = mrow0 + wm * 32 + (lane >> 2);
    const int n_base = nrow0 + wn * 64 + (lane & 3) * 2;
#pragma unroll
    for (int i = 0; i < 2; i++) {
#pragma unroll
        for (int j = 0; j < 8; j++) {
            int n0 = n_base + j * 8;
            float b0 = bias[n0], b1 = bias[n0 + 1];
            int m0 = m_base + i * 16;
            float2 lo2 = {acc[i][j][0] + b0, acc[i][j][1] + b1};
            float2 hi2 = {acc[i][j][2] + b0, acc[i][j][3] + b1};
            *reinterpret_cast<float2*>(C + (size_t)m0 * N_DIM + n0)       = lo2;
            *reinterpret_cast<float2*>(C + (size_t)(m0 + 8) * N_DIM + n0) = hi2;
        }
    }
}

// -------- correction GEMM: C += (A8 @ B8^T) * 2^-14 (e4m3, K_eff=4096) ---
__global__ __launch_bounds__(256, 2)
void gemm_corr_kernel(float* __restrict__ C)
{
    extern __shared__ __align__(128) char sm[];
    const uint32_t smem_base = smem_u32(sm);
    const int tid = threadIdx.x, wid = tid >> 5, lane = tid & 31;
    const int wm = wid & 3, wn = wid >> 2;
    const int mrow0 = blockIdx.x * BM;
    const int nrow0 = blockIdx.y * BN;

    float acc[2][8][4];
#pragma unroll
    for (int i = 0; i < 2; i++)
#pragma unroll
        for (int j = 0; j < 8; j++)
#pragma unroll
            for (int r = 0; r < 4; r++) acc[i][j][r] = 0.0f;

    auto prefetch = [&](int c) {
        const uint32_t base = smem_base + (c % NSTAGE) * STG;
#pragma unroll
        for (int i = 0; i < 4; i++) {
            int idx = tid + i * 256; int r = idx >> 3, u = idx & 7;
            CP_ASYNC16(base + SWZ(r * 128 + u * 16),
                       g_a8 + (size_t)(mrow0 + r) * 4096 + c * 128 + u * 16);
        }
#pragma unroll
        for (int i = 0; i < 4; i++) {
            int idx = tid + i * 256; int r = idx >> 3, u = idx & 7;
            CP_ASYNC16(base + A_ST + SWZ(r * 128 + u * 16),
                       g_b8 + (size_t)(nrow0 + r) * 4096 + c * 128 + u * 16);
        }
    };

    prefetch(0); CP_COMMIT();
    prefetch(1); CP_COMMIT();

    const int a_row = wm * 32 + (lane & 15);
    const int a_kb  = (lane >> 4) * 16;
    const int b_row = wn * 64 + (lane & 7) + ((lane >> 4) << 3);
    const int b_kb  = ((lane >> 3) & 1) * 16;

    for (int c = 0; c < NCHUNK; ++c) {
        if (c + 2 < NCHUNK) prefetch(c + 2);
        CP_COMMIT();
        CP_WAIT(2);
        __syncthreads();

        const uint32_t aB = smem_base + (c % NSTAGE) * STG;
        const uint32_t bB = aB + A_ST;
#pragma unroll
        for (int ks = 0; ks < 4; ++ks) {             // each ks = k32 fp8
            uint32_t a[2][4], b[4][4];
#pragma unroll
            for (int i = 0; i < 2; i++)
                LDSM_X4(a[i][0], a[i][1], a[i][2], a[i][3],
                        aB + SWZ((a_row + i * 16) * 128 + ks * 32 + a_kb));
#pragma unroll
            for (int j = 0; j < 4; j++)
                LDSM_X4(b[j][0], b[j][1], b[j][2], b[j][3],
                        bB + SWZ((b_row + j * 16) * 128 + ks * 32 + b_kb));
#pragma unroll
            for (int i = 0; i < 2; i++)
#pragma unroll
                for (int j = 0; j < 4; j++) {
                    QMMA16832(acc[i][2 * j + 0], a[i], b[j][0], b[j][1]);
                    QMMA16832(acc[i][2 * j + 1], a[i], b[j][2], b[j][3]);
                }
        }
        __syncthreads();
    }

    const int m_base = mrow0 + wm * 32 + (lane >> 2);
    const int n_base = nrow0 + wn * 64 + (lane & 3) * 2;
#pragma unroll
    for (int i = 0; i < 2; i++) {
#pragma unroll
        for (int j = 0; j < 8; j++) {
            int n0 = n_base + j * 8;
            int m0 = m_base + i * 16;
            float2* p0 = reinterpret_cast<float2*>(C + (size_t)m0 * N_DIM + n0);
            float2* p1 = reinterpret_cast<float2*>(C + (size_t)(m0 + 8) * N_DIM + n0);
            float2 v0 = *p0, v1 = *p1;
            v0.x += acc[i][j][0] * CORR_INV;  v0.y += acc[i][j][1] * CORR_INV;
            v1.x += acc[i][j][2] * CORR_INV;  v1.y += acc[i][j][3] * CORR_INV;
            *p0 = v0;  *p1 = v1;
        }
    }
}

// -------- GroupNorm + SiLU + mult + SiLU (warp per group, in place) ------
__device__ __forceinline__ float sigmoidf_(float x) { return 1.0f / (1.0f + expf(-x)); }

__global__ __launch_bounds__(512)
void gn_silu_kernel(float* __restrict__ y,
                    const float* __restrict__ gn_w,
                    const float* __restrict__ gn_b,
                    const float* __restrict__ mult_w)
{
    const int row = blockIdx.x;
    const int w   = threadIdx.x >> 5;
    const int lane = threadIdx.x & 31;

    float4* p = reinterpret_cast<float4*>(y + (size_t)row * N_DIM + w * GSIZE);
    float4 v[4];
#pragma unroll
    for (int t = 0; t < 4; t++) v[t] = p[lane + t * 32];

    float s = 0.0f, ss = 0.0f;
#pragma unroll
    for (int t = 0; t < 4; t++) {
        s  += v[t].x + v[t].y + v[t].z + v[t].w;
        ss += v[t].x*v[t].x + v[t].y*v[t].y + v[t].z*v[t].z + v[t].w*v[t].w;
    }
#pragma unroll
    for (int o = 16; o > 0; o >>= 1) {
        s  += __shfl_xor_sync(0xffffffffu, s,  o);
        ss += __shfl_xor_sync(0xffffffffu, ss, o);
    }
    const float inv_n = 1.0f / (float)GSIZE;
    const float mean  = s * inv_n;
    const float var   = fmaxf(ss * inv_n - mean * mean, 0.0f);
    const float rstd  = rsqrtf(var + EPS);

#pragma unroll
    for (int t = 0; t < 4; t++) {
        float vv[4] = {v[t].x, v[t].y, v[t].z, v[t].w};
        float out[4];
        const int c0 = w * GSIZE + (lane + t * 32) * 4;
#pragma unroll
        for (int j = 0; j < 4; j++) {
            int c = c0 + j;
            float n  = (vv[j] - mean) * rstd * gn_w[c] + gn_b[c];
            float s1 = n * sigmoidf_(n);
            float m  = s1 * mult_w[c];
            out[j]   = m * sigmoidf_(m);
        }
        float4 o = {out[0], out[1], out[2], out[3]};
        p[lane + t * 32] = o;
    }
}

// -------------------------------------------------------------------------
extern "C" void kernel_launch(void* const* d_in, const int* in_sizes, int n_in,
                              void* d_out, int out_size)
{
    const float* x      = (const float*)d_in[0];
    const float* W      = (const float*)d_in[1];
    const float* b      = (const float*)d_in[2];
    const float* gn_w   = (const float*)d_in[3];
    const float* gn_b   = (const float*)d_in[4];
    const float* mult_w = (const float*)d_in[5];
    float* out = (float*)d_out;

    __nv_bfloat16 *xh, *wh;
    uint8_t *a8, *b8;
    cudaGetSymbolAddress((void**)&xh, g_xh);
    cudaGetSymbolAddress((void**)&wh, g_wh);
    cudaGetSymbolAddress((void**)&a8, g_a8);
    cudaGetSymbolAddress((void**)&b8, g_b8);

    int n8x = (M_DIM * K_DIM) / 8;
    int n8w = (N_DIM * K_DIM) / 8;
    split_kernel<<<(n8x + 255) / 256, 256>>>(x, xh, a8, n8x, 1.0f, 512.0f, 0);
    split_kernel<<<(n8w + 255) / 256, 256>>>(W, wh, b8, n8w, 32.0f, 16384.0f, 1);

    cudaFuncSetAttribute(gemm_main_kernel,
                         cudaFuncAttributeMaxDynamicSharedMemorySize, SMEM_GEMM);
    cudaFuncSetAttribute(gemm_corr_kernel,
                         cudaFuncAttributeMaxDynamicSharedMemorySize, SMEM_GEMM);

    dim3 ggrid(M_DIM / BM, N_DIM / BN);   // (32, 64)
    gemm_main_kernel<<<ggrid, 256, SMEM_GEMM>>>(b, out);
    gemm_corr_kernel<<<ggrid, 256, SMEM_GEMM>>>(out);

    gn_silu_kernel<<<M_DIM, 512>>>(out, gn_w, gn_b, mult_w);
}

// round 6
// speedup vs baseline: 3.0329x; 1.8841x over previous
#include <cuda_runtime.h>
#include <cuda_fp16.h>
#include <cstdint>
#include <math.h>

// Problem constants: B=4096, IN_F=2048, OUT_F=8192, NG=16
#define M_DIM   4096
#define K_DIM   2048
#define N_DIM   8192
#define NGROUPS 16
#define GSIZE   (N_DIM / NGROUPS)   // 512
#define EPS     1e-5f

// GEMM tiling: CTA 128x128, 8 warps of 32x64 (4M x 2N)
#define BM 128
#define BN 128
#define CHUNK 64                    // K elems per chunk = 128 B rows (fp16)
#define NCHUNK (K_DIM / CHUNK)      // 32
#define A_ST (BM * 128)             // 16 KB
#define B_ST (BN * 128)             // 16 KB
#define STG  (A_ST + B_ST)          // 32 KB
#define NSTAGE 3
#define SMEM_GEMM (NSTAGE * STG)    // 98304 -> 2 CTAs/SM

#define SWZ(o) ((o) ^ ((((uint32_t)(o)) >> 3) & 0x70))

// -------- scratch: fp16 copies of x and W --------------------------------
__device__ __half g_x16[(size_t)M_DIM * K_DIM];     // 16 MB
__device__ __half g_w16[(size_t)N_DIM * K_DIM];     // 32 MB

// -------- PTX helpers (plain sm_80 PTX) ----------------------------------
__device__ __forceinline__ uint32_t smem_u32(const void* p) {
    uint32_t a;
    asm("{ .reg .u64 t; cvta.to.shared.u64 t, %1; cvt.u32.u64 %0, t; }" : "=r"(a) : "l"(p));
    return a;
}
#define CP_ASYNC16(dst, src) \
    asm volatile("cp.async.cg.shared.global [%0], [%1], 16;" :: "r"(dst), "l"(src) : "memory")
#define CP_COMMIT() asm volatile("cp.async.commit_group;" ::: "memory")
#define CP_WAIT(n)  asm volatile("cp.async.wait_group %0;" :: "n"(n) : "memory")

#define LDSM_X4(r0, r1, r2, r3, addr) \
    asm volatile("ldmatrix.sync.aligned.m8n8.x4.shared.b16 {%0,%1,%2,%3}, [%4];" \
        : "=r"(r0), "=r"(r1), "=r"(r2), "=r"(r3) : "r"(addr))

#define MMA16816F16(d, a, b0v, b1v) \
    asm volatile("mma.sync.aligned.m16n8k16.row.col.f32.f16.f16.f32 " \
        "{%0,%1,%2,%3}, {%4,%5,%6,%7}, {%8,%9}, {%0,%1,%2,%3};" \
        : "+f"((d)[0]), "+f"((d)[1]), "+f"((d)[2]), "+f"((d)[3]) \
        : "r"((a)[0]), "r"((a)[1]), "r"((a)[2]), "r"((a)[3]), "r"(b0v), "r"(b1v))

// -------- convert: fp32 -> fp16 (8 elems per thread) ---------------------
__global__ __launch_bounds__(256)
void cvt_kernel(const float* __restrict__ src, __half* __restrict__ dst, int n8)
{
    int i = blockIdx.x * 256 + threadIdx.x;
    if (i >= n8) return;
    const float4 v0 = reinterpret_cast<const float4*>(src)[i * 2];
    const float4 v1 = reinterpret_cast<const float4*>(src)[i * 2 + 1];
    __half2 h0 = __floats2half2_rn(v0.x, v0.y);
    __half2 h1 = __floats2half2_rn(v0.z, v0.w);
    __half2 h2 = __floats2half2_rn(v1.x, v1.y);
    __half2 h3 = __floats2half2_rn(v1.z, v1.w);
    uint4 u;
    u.x = *reinterpret_cast<uint32_t*>(&h0);
    u.y = *reinterpret_cast<uint32_t*>(&h1);
    u.z = *reinterpret_cast<uint32_t*>(&h2);
    u.w = *reinterpret_cast<uint32_t*>(&h3);
    reinterpret_cast<uint4*>(dst)[i] = u;
}

// -------- GEMM: C = x16 @ W16^T + bias (fp16 in, fp32 accum) -------------
__global__ __launch_bounds__(256, 2)
void gemm_f16_kernel(const float* __restrict__ bias, float* __restrict__ C)
{
    extern __shared__ __align__(128) char sm[];
    const uint32_t smem_base = smem_u32(sm);
    const int tid = threadIdx.x, wid = tid >> 5, lane = tid & 31;
    const int wm = wid & 3, wn = wid >> 2;           // 4M x 2N warps, 32x64 each
    const int mrow0 = blockIdx.x * BM;
    const int nrow0 = blockIdx.y * BN;

    float acc[2][8][4];
#pragma unroll
    for (int i = 0; i < 2; i++)
#pragma unroll
        for (int j = 0; j < 8; j++)
#pragma unroll
            for (int r = 0; r < 4; r++) acc[i][j][r] = 0.0f;

    auto prefetch = [&](int c) {
        const uint32_t base = smem_base + (c % NSTAGE) * STG;
        const int k0 = c * CHUNK;
#pragma unroll
        for (int i = 0; i < 4; i++) {
            int idx = tid + i * 256; int r = idx >> 3, u = idx & 7;
            CP_ASYNC16(base + SWZ(r * 128 + u * 16),
                       &g_x16[(size_t)(mrow0 + r) * K_DIM + k0 + u * 8]);
        }
#pragma unroll
        for (int i = 0; i < 4; i++) {
            int idx = tid + i * 256; int r = idx >> 3, u = idx & 7;
            CP_ASYNC16(base + A_ST + SWZ(r * 128 + u * 16),
                       &g_w16[(size_t)(nrow0 + r) * K_DIM + k0 + u * 8]);
        }
    };

    prefetch(0); CP_COMMIT();
    prefetch(1); CP_COMMIT();

    const int a_row = wm * 32 + (lane & 15);
    const int a_kb  = (lane >> 4) * 16;
    const int b_row = wn * 64 + (lane & 7) + ((lane >> 4) << 3);
    const int b_kb  = ((lane >> 3) & 1) * 16;

    for (int c = 0; c < NCHUNK; ++c) {
        if (c + 2 < NCHUNK) prefetch(c + 2);
        CP_COMMIT();
        CP_WAIT(2);
        __syncthreads();

        const uint32_t aB = smem_base + (c % NSTAGE) * STG;
        const uint32_t bB = aB + A_ST;
#pragma unroll
        for (int ks = 0; ks < 4; ++ks) {
            uint32_t a[2][4], b[4][4];
#pragma unroll
            for (int i = 0; i < 2; i++)
                LDSM_X4(a[i][0], a[i][1], a[i][2], a[i][3],
                        aB + SWZ((a_row + i * 16) * 128 + ks * 32 + a_kb));
#pragma unroll
            for (int j = 0; j < 4; j++)
                LDSM_X4(b[j][0], b[j][1], b[j][2], b[j][3],
                        bB + SWZ((b_row + j * 16) * 128 + ks * 32 + b_kb));
#pragma unroll
            for (int i = 0; i < 2; i++)
#pragma unroll
                for (int j = 0; j < 4; j++) {
                    MMA16816F16(acc[i][2 * j + 0], a[i], b[j][0], b[j][1]);
                    MMA16816F16(acc[i][2 * j + 1], a[i], b[j][2], b[j][3]);
                }
        }
        __syncthreads();
    }

    const int m_base = mrow0 + wm * 32 + (lane >> 2);
    const int n_base = nrow0 + wn * 64 + (lane & 3) * 2;
#pragma unroll
    for (int i = 0; i < 2; i++) {
#pragma unroll
        for (int j = 0; j < 8; j++) {
            int n0 = n_base + j * 8;
            float b0 = bias[n0], b1 = bias[n0 + 1];
            int m0 = m_base + i * 16;
            float2 lo2 = {acc[i][j][0] + b0, acc[i][j][1] + b1};
            float2 hi2 = {acc[i][j][2] + b0, acc[i][j][3] + b1};
            *reinterpret_cast<float2*>(C + (size_t)m0 * N_DIM + n0)       = lo2;
            *reinterpret_cast<float2*>(C + (size_t)(m0 + 8) * N_DIM + n0) = hi2;
        }
    }
}

// -------- GroupNorm + SiLU + mult + SiLU (warp per group, in place) ------
__device__ __forceinline__ float sigmoidf_(float x) { return 1.0f / (1.0f + expf(-x)); }

__global__ __launch_bounds__(512)
void gn_silu_kernel(float* __restrict__ y,
                    const float* __restrict__ gn_w,
                    const float* __restrict__ gn_b,
                    const float* __restrict__ mult_w)
{
    const int row = blockIdx.x;
    const int w   = threadIdx.x >> 5;
    const int lane = threadIdx.x & 31;

    float4* p = reinterpret_cast<float4*>(y + (size_t)row * N_DIM + w * GSIZE);
    float4 v[4];
#pragma unroll
    for (int t = 0; t < 4; t++) v[t] = p[lane + t * 32];

    float s = 0.0f, ss = 0.0f;
#pragma unroll
    for (int t = 0; t < 4; t++) {
        s  += v[t].x + v[t].y + v[t].z + v[t].w;
        ss += v[t].x*v[t].x + v[t].y*v[t].y + v[t].z*v[t].z + v[t].w*v[t].w;
    }
#pragma unroll
    for (int o = 16; o > 0; o >>= 1) {
        s  += __shfl_xor_sync(0xffffffffu, s,  o);
        ss += __shfl_xor_sync(0xffffffffu, ss, o);
    }
    const float inv_n = 1.0f / (float)GSIZE;
    const float mean  = s * inv_n;
    const float var   = fmaxf(ss * inv_n - mean * mean, 0.0f);
    const float rstd  = rsqrtf(var + EPS);

#pragma unroll
    for (int t = 0; t < 4; t++) {
        float vv[4] = {v[t].x, v[t].y, v[t].z, v[t].w};
        float out[4];
        const int c0 = w * GSIZE + (lane + t * 32) * 4;
#pragma unroll
        for (int j = 0; j < 4; j++) {
            int c = c0 + j;
            float n  = (vv[j] - mean) * rstd * gn_w[c] + gn_b[c];
            float s1 = n * sigmoidf_(n);
            float m  = s1 * mult_w[c];
            out[j]   = m * sigmoidf_(m);
        }
        float4 o = {out[0], out[1], out[2], out[3]};
        p[lane + t * 32] = o;
    }
}

// -------------------------------------------------------------------------
extern "C" void kernel_launch(void* const* d_in, const int* in_sizes, int n_in,
                              void* d_out, int out_size)
{
    const float* x      = (const float*)d_in[0];
    const float* W      = (const float*)d_in[1];
    const float* b      = (const float*)d_in[2];
    const float* gn_w   = (const float*)d_in[3];
    const float* gn_b   = (const float*)d_in[4];
    const float* mult_w = (const float*)d_in[5];
    float* out = (float*)d_out;

    __half *x16, *w16;
    cudaGetSymbolAddress((void**)&x16, g_x16);
    cudaGetSymbolAddress((void**)&w16, g_w16);

    int n8x = (M_DIM * K_DIM) / 8;
    int n8w = (N_DIM * K_DIM) / 8;
    cvt_kernel<<<(n8x + 255) / 256, 256>>>(x, x16, n8x);
    cvt_kernel<<<(n8w + 255) / 256, 256>>>(W, w16, n8w);

    cudaFuncSetAttribute(gemm_f16_kernel,
                         cudaFuncAttributeMaxDynamicSharedMemorySize, SMEM_GEMM);

    dim3 ggrid(M_DIM / BM, N_DIM / BN);   // (32, 64)
    gemm_f16_kernel<<<ggrid, 256, SMEM_GEMM>>>(b, out);

    gn_silu_kernel<<<M_DIM, 512>>>(out, gn_w, gn_b, mult_w);
}

// round 7
// speedup vs baseline: 4.7855x; 1.5779x over previous
#include <cuda_runtime.h>
#include <cuda_fp16.h>
#include <cstdint>
#include <math.h>

// Problem constants: B=4096, IN_F=2048, OUT_F=8192, NG=16
#define M_DIM   4096
#define K_DIM   2048
#define N_DIM   8192
#define NGROUPS 16
#define GSIZE   (N_DIM / NGROUPS)   // 512
#define EPS     1e-5f

// GEMM tiling: CTA 128x128, 8 warps of 32x64 (4M x 2N)
#define BM 128
#define BN 128
#define CHUNK 64                    // K elems per chunk = 128 B rows (fp16)
#define NCHUNK (K_DIM / CHUNK)      // 32
#define A_ST (BM * 128)             // 16 KB
#define B_ST (BN * 128)             // 16 KB
#define STG  (A_ST + B_ST)          // 32 KB
#define NSTAGE 3
#define SMEM_GEMM (NSTAGE * STG)    // 98304 -> 2 CTAs/SM

#define SWZ(o) ((o) ^ ((((uint32_t)(o)) >> 3) & 0x70))

// -------- scratch: fp16 copies of x and W --------------------------------
__device__ __half g_x16[(size_t)M_DIM * K_DIM];     // 16 MB
__device__ __half g_w16[(size_t)N_DIM * K_DIM];     // 32 MB

// -------- PTX helpers (plain sm_80 PTX) ----------------------------------
__device__ __forceinline__ uint32_t smem_u32(const void* p) {
    uint32_t a;
    asm("{ .reg .u64 t; cvta.to.shared.u64 t, %1; cvt.u32.u64 %0, t; }" : "=r"(a) : "l"(p));
    return a;
}
#define CP_ASYNC16(dst, src) \
    asm volatile("cp.async.cg.shared.global [%0], [%1], 16;" :: "r"(dst), "l"(src) : "memory")
#define CP_COMMIT() asm volatile("cp.async.commit_group;" ::: "memory")
#define CP_WAIT(n)  asm volatile("cp.async.wait_group %0;" :: "n"(n) : "memory")

#define LDSM_X4(r0, r1, r2, r3, addr) \
    asm volatile("ldmatrix.sync.aligned.m8n8.x4.shared.b16 {%0,%1,%2,%3}, [%4];" \
        : "=r"(r0), "=r"(r1), "=r"(r2), "=r"(r3) : "r"(addr))

#define MMA16816F16(d, a, b0v, b1v) \
    asm volatile("mma.sync.aligned.m16n8k16.row.col.f32.f16.f16.f32 " \
        "{%0,%1,%2,%3}, {%4,%5,%6,%7}, {%8,%9}, {%0,%1,%2,%3};" \
        : "+f"((d)[0]), "+f"((d)[1]), "+f"((d)[2]), "+f"((d)[3]) \
        : "r"((a)[0]), "r"((a)[1]), "r"((a)[2]), "r"((a)[3]), "r"(b0v), "r"(b1v))

// -------- convert: fp32 -> fp16 (8 elems per thread) ---------------------
__global__ __launch_bounds__(256)
void cvt_kernel(const float* __restrict__ src, __half* __restrict__ dst, int n8)
{
    int i = blockIdx.x * 256 + threadIdx.x;
    if (i >= n8) return;
    const float4 v0 = reinterpret_cast<const float4*>(src)[i * 2];
    const float4 v1 = reinterpret_cast<const float4*>(src)[i * 2 + 1];
    __half2 h0 = __floats2half2_rn(v0.x, v0.y);
    __half2 h1 = __floats2half2_rn(v0.z, v0.w);
    __half2 h2 = __floats2half2_rn(v1.x, v1.y);
    __half2 h3 = __floats2half2_rn(v1.z, v1.w);
    uint4 u;
    u.x = *reinterpret_cast<uint32_t*>(&h0);
    u.y = *reinterpret_cast<uint32_t*>(&h1);
    u.z = *reinterpret_cast<uint32_t*>(&h2);
    u.w = *reinterpret_cast<uint32_t*>(&h3);
    reinterpret_cast<uint4*>(dst)[i] = u;
}

// -------- GEMM: C = x16 @ W16^T + bias (fp16 in, fp32 accum) -------------
__global__ __launch_bounds__(256, 2)
void gemm_f16_kernel(const float* __restrict__ bias, float* __restrict__ C)
{
    extern __shared__ __align__(128) char sm[];
    const uint32_t smem_base = smem_u32(sm);
    const int tid = threadIdx.x, wid = tid >> 5, lane = tid & 31;
    const int wm = wid & 3, wn = wid >> 2;           // 4M x 2N warps, 32x64 each
    const int mrow0 = blockIdx.x * BM;
    const int nrow0 = blockIdx.y * BN;

    float acc[2][8][4];
#pragma unroll
    for (int i = 0; i < 2; i++)
#pragma unroll
        for (int j = 0; j < 8; j++)
#pragma unroll
            for (int r = 0; r < 4; r++) acc[i][j][r] = 0.0f;

    auto prefetch = [&](int c) {
        const uint32_t base = smem_base + (c % NSTAGE) * STG;
        const int k0 = c * CHUNK;
#pragma unroll
        for (int i = 0; i < 4; i++) {
            int idx = tid + i * 256; int r = idx >> 3, u = idx & 7;
            CP_ASYNC16(base + SWZ(r * 128 + u * 16),
                       &g_x16[(size_t)(mrow0 + r) * K_DIM + k0 + u * 8]);
        }
#pragma unroll
        for (int i = 0; i < 4; i++) {
            int idx = tid + i * 256; int r = idx >> 3, u = idx & 7;
            CP_ASYNC16(base + A_ST + SWZ(r * 128 + u * 16),
                       &g_w16[(size_t)(nrow0 + r) * K_DIM + k0 + u * 8]);
        }
    };

    prefetch(0); CP_COMMIT();
    prefetch(1); CP_COMMIT();

    const int a_row = wm * 32 + (lane & 15);
    const int a_kb  = (lane >> 4) * 16;
    const int b_row = wn * 64 + (lane & 7) + ((lane >> 4) << 3);
    const int b_kb  = ((lane >> 3) & 1) * 16;

    for (int c = 0; c < NCHUNK; ++c) {
        // stage c complete (<=1 group may remain in flight), and by this
        // barrier every warp has finished reading stage c-1, so issuing
        // prefetch(c+2) -> buffer (c+2)%3 == (c-1)%3 below is safe.
        CP_WAIT(1);
        __syncthreads();

        const uint32_t aB = smem_base + (c % NSTAGE) * STG;
        const uint32_t bB = aB + A_ST;
#pragma unroll
        for (int ks = 0; ks < 4; ++ks) {
            uint32_t a[2][4], b[4][4];
#pragma unroll
            for (int i = 0; i < 2; i++)
                LDSM_X4(a[i][0], a[i][1], a[i][2], a[i][3],
                        aB + SWZ((a_row + i * 16) * 128 + ks * 32 + a_kb));
#pragma unroll
            for (int j = 0; j < 4; j++)
                LDSM_X4(b[j][0], b[j][1], b[j][2], b[j][3],
                        bB + SWZ((b_row + j * 16) * 128 + ks * 32 + b_kb));
#pragma unroll
            for (int i = 0; i < 2; i++)
#pragma unroll
                for (int j = 0; j < 4; j++) {
                    MMA16816F16(acc[i][2 * j + 0], a[i], b[j][0], b[j][1]);
                    MMA16816F16(acc[i][2 * j + 1], a[i], b[j][2], b[j][3]);
                }
        }

        if (c + 2 < NCHUNK) { prefetch(c + 2); CP_COMMIT(); }
    }

    const int m_base = mrow0 + wm * 32 + (lane >> 2);
    const int n_base = nrow0 + wn * 64 + (lane & 3) * 2;
#pragma unroll
    for (int i = 0; i < 2; i++) {
#pragma unroll
        for (int j = 0; j < 8; j++) {
            int n0 = n_base + j * 8;
            float b0 = bias[n0], b1 = bias[n0 + 1];
            int m0 = m_base + i * 16;
            float2 lo2 = {acc[i][j][0] + b0, acc[i][j][1] + b1};
            float2 hi2 = {acc[i][j][2] + b0, acc[i][j][3] + b1};
            *reinterpret_cast<float2*>(C + (size_t)m0 * N_DIM + n0)       = lo2;
            *reinterpret_cast<float2*>(C + (size_t)(m0 + 8) * N_DIM + n0) = hi2;
        }
    }
}

// -------- GroupNorm + SiLU + mult + SiLU (warp per group, in place) ------
// fast sigmoid: MUFU-based exp + fast divide (~2e-7 rel err, negligible
// against the 3e-4 fp16-GEMM error).
__device__ __forceinline__ float fast_sigmoid(float x) {
    float e = __expf(-x);
    return __fdividef(1.0f, 1.0f + e);
}

__global__ __launch_bounds__(512)
void gn_silu_kernel(float* __restrict__ y,
                    const float* __restrict__ gn_w,
                    const float* __restrict__ gn_b,
                    const float* __restrict__ mult_w)
{
    const int row = blockIdx.x;
    const int w   = threadIdx.x >> 5;
    const int lane = threadIdx.x & 31;

    float4* p = reinterpret_cast<float4*>(y + (size_t)row * N_DIM + w * GSIZE);
    float4 v[4];
#pragma unroll
    for (int t = 0; t < 4; t++) v[t] = p[lane + t * 32];

    float s = 0.0f, ss = 0.0f;
#pragma unroll
    for (int t = 0; t < 4; t++) {
        s  += v[t].x + v[t].y + v[t].z + v[t].w;
        ss += v[t].x*v[t].x + v[t].y*v[t].y + v[t].z*v[t].z + v[t].w*v[t].w;
    }
#pragma unroll
    for (int o = 16; o > 0; o >>= 1) {
        s  += __shfl_xor_sync(0xffffffffu, s,  o);
        ss += __shfl_xor_sync(0xffffffffu, ss, o);
    }
    const float inv_n = 1.0f / (float)GSIZE;
    const float mean  = s * inv_n;
    const float var   = fmaxf(ss * inv_n - mean * mean, 0.0f);
    const float rstd  = rsqrtf(var + EPS);

#pragma unroll
    for (int t = 0; t < 4; t++) {
        float vv[4] = {v[t].x, v[t].y, v[t].z, v[t].w};
        float out[4];
        const int c0 = w * GSIZE + (lane + t * 32) * 4;
#pragma unroll
        for (int j = 0; j < 4; j++) {
            int c = c0 + j;
            float n  = (vv[j] - mean) * rstd * gn_w[c] + gn_b[c];
            float s1 = n * fast_sigmoid(n);
            float m  = s1 * mult_w[c];
            out[j]   = m * fast_sigmoid(m);
        }
        float4 o = {out[0], out[1], out[2], out[3]};
        p[lane + t * 32] = o;
    }
}

// -------------------------------------------------------------------------
extern "C" void kernel_launch(void* const* d_in, const int* in_sizes, int n_in,
                              void* d_out, int out_size)
{
    const float* x      = (const float*)d_in[0];
    const float* W      = (const float*)d_in[1];
    const float* b      = (const float*)d_in[2];
    const float* gn_w   = (const float*)d_in[3];
    const float* gn_b   = (const float*)d_in[4];
    const float* mult_w = (const float*)d_in[5];
    float* out = (float*)d_out;

    __half *x16, *w16;
    cudaGetSymbolAddress((void**)&x16, g_x16);
    cudaGetSymbolAddress((void**)&w16, g_w16);

    int n8x = (M_DIM * K_DIM) / 8;
    int n8w = (N_DIM * K_DIM) / 8;
    cvt_kernel<<<(n8x + 255) / 256, 256>>>(x, x16, n8x);
    cvt_kernel<<<(n8w + 255) / 256, 256>>>(W, w16, n8w);

    cudaFuncSetAttribute(gemm_f16_kernel,
                         cudaFuncAttributeMaxDynamicSharedMemorySize, SMEM_GEMM);

    dim3 ggrid(M_DIM / BM, N_DIM / BN);   // (32, 64)
    gemm_f16_kernel<<<ggrid, 256, SMEM_GEMM>>>(b, out);

    gn_silu_kernel<<<M_DIM, 512>>>(out, gn_w, gn_b, mult_w);
}

// round 8
// speedup vs baseline: 4.9421x; 1.0327x over previous
#include <cuda_runtime.h>
#include <cuda_fp16.h>
#include <cstdint>
#include <math.h>

// Problem constants: B=4096, IN_F=2048, OUT_F=8192, NG=16
#define M_DIM   4096
#define K_DIM   2048
#define N_DIM   8192
#define NGROUPS 16
#define GSIZE   (N_DIM / NGROUPS)   // 512
#define EPS     1e-5f

// GEMM tiling: CTA 128x128, 8 warps of 32x64 (4M x 2N)
#define BM 128
#define BN 128
#define CHUNK 64                    // K elems per chunk = 128 B rows (fp16)
#define NCHUNK (K_DIM / CHUNK)      // 32
#define A_ST (BM * 128)             // 16 KB
#define B_ST (BN * 128)             // 16 KB
#define STG  (A_ST + B_ST)          // 32 KB
#define NSTAGE 3
#define SMEM_GEMM (NSTAGE * STG)    // 98304 -> 2 CTAs/SM

#define SWZ(o) ((o) ^ ((((uint32_t)(o)) >> 3) & 0x70))

// -------- scratch: fp16 copies of x and W --------------------------------
__device__ __half g_x16[(size_t)M_DIM * K_DIM];     // 16 MB
__device__ __half g_w16[(size_t)N_DIM * K_DIM];     // 32 MB

// -------- PTX helpers (plain sm_80 PTX) ----------------------------------
__device__ __forceinline__ uint32_t smem_u32(const void* p) {
    uint32_t a;
    asm("{ .reg .u64 t; cvta.to.shared.u64 t, %1; cvt.u32.u64 %0, t; }" : "=r"(a) : "l"(p));
    return a;
}
#define CP_ASYNC16(dst, src) \
    asm volatile("cp.async.cg.shared.global [%0], [%1], 16;" :: "r"(dst), "l"(src) : "memory")
#define CP_COMMIT() asm volatile("cp.async.commit_group;" ::: "memory")
#define CP_WAIT(n)  asm volatile("cp.async.wait_group %0;" :: "n"(n) : "memory")

#define LDSM_X4(r0, r1, r2, r3, addr) \
    asm volatile("ldmatrix.sync.aligned.m8n8.x4.shared.b16 {%0,%1,%2,%3}, [%4];" \
        : "=r"(r0), "=r"(r1), "=r"(r2), "=r"(r3) : "r"(addr))

#define MMA16816F16(d, a, b0v, b1v) \
    asm volatile("mma.sync.aligned.m16n8k16.row.col.f32.f16.f16.f32 " \
        "{%0,%1,%2,%3}, {%4,%5,%6,%7}, {%8,%9}, {%0,%1,%2,%3};" \
        : "+f"((d)[0]), "+f"((d)[1]), "+f"((d)[2]), "+f"((d)[3]) \
        : "r"((a)[0]), "r"((a)[1]), "r"((a)[2]), "r"((a)[3]), "r"(b0v), "r"(b1v))

// -------- convert: fp32 -> fp16, both tensors in ONE launch --------------
// i in [0, n8x) -> x ; i in [n8x, n8x+n8w) -> W.
__global__ __launch_bounds__(256)
void cvt_both_kernel(const float* __restrict__ x, __half* __restrict__ x16,
                     const float* __restrict__ W, __half* __restrict__ w16,
                     int n8x, int n8tot)
{
    int i = blockIdx.x * 256 + threadIdx.x;
    if (i >= n8tot) return;
    const float* src;
    __half* dst;
    int idx;
    if (i < n8x) { src = x; dst = x16; idx = i; }
    else         { src = W; dst = w16; idx = i - n8x; }

    const float4 v0 = reinterpret_cast<const float4*>(src)[idx * 2];
    const float4 v1 = reinterpret_cast<const float4*>(src)[idx * 2 + 1];
    __half2 h0 = __floats2half2_rn(v0.x, v0.y);
    __half2 h1 = __floats2half2_rn(v0.z, v0.w);
    __half2 h2 = __floats2half2_rn(v1.x, v1.y);
    __half2 h3 = __floats2half2_rn(v1.z, v1.w);
    uint4 u;
    u.x = *reinterpret_cast<uint32_t*>(&h0);
    u.y = *reinterpret_cast<uint32_t*>(&h1);
    u.z = *reinterpret_cast<uint32_t*>(&h2);
    u.w = *reinterpret_cast<uint32_t*>(&h3);
    reinterpret_cast<uint4*>(dst)[idx] = u;
}

// -------- GEMM: C = x16 @ W16^T + bias (fp16 in, fp32 accum) -------------
__global__ __launch_bounds__(256, 2)
void gemm_f16_kernel(const float* __restrict__ bias, float* __restrict__ C)
{
    extern __shared__ __align__(128) char sm[];
    const uint32_t smem_base = smem_u32(sm);
    const int tid = threadIdx.x, wid = tid >> 5, lane = tid & 31;
    const int wm = wid & 3, wn = wid >> 2;           // 4M x 2N warps, 32x64 each
    const int mrow0 = blockIdx.x * BM;
    const int nrow0 = blockIdx.y * BN;

    float acc[2][8][4];
#pragma unroll
    for (int i = 0; i < 2; i++)
#pragma unroll
        for (int j = 0; j < 8; j++)
#pragma unroll
            for (int r = 0; r < 4; r++) acc[i][j][r] = 0.0f;

    auto prefetch = [&](int c) {
        const uint32_t base = smem_base + (c % NSTAGE) * STG;
        const int k0 = c * CHUNK;
#pragma unroll
        for (int i = 0; i < 4; i++) {
            int idx = tid + i * 256; int r = idx >> 3, u = idx & 7;
            CP_ASYNC16(base + SWZ(r * 128 + u * 16),
                       &g_x16[(size_t)(mrow0 + r) * K_DIM + k0 + u * 8]);
        }
#pragma unroll
        for (int i = 0; i < 4; i++) {
            int idx = tid + i * 256; int r = idx >> 3, u = idx & 7;
            CP_ASYNC16(base + A_ST + SWZ(r * 128 + u * 16),
                       &g_w16[(size_t)(nrow0 + r) * K_DIM + k0 + u * 8]);
        }
    };

    prefetch(0); CP_COMMIT();
    prefetch(1); CP_COMMIT();

    const int a_row = wm * 32 + (lane & 15);
    const int a_kb  = (lane >> 4) * 16;
    const int b_row = wn * 64 + (lane & 7) + ((lane >> 4) << 3);
    const int b_kb  = ((lane >> 3) & 1) * 16;

    for (int c = 0; c < NCHUNK; ++c) {
        // stage c complete; by this barrier every warp finished reading
        // stage c-1, so prefetch(c+2) into buffer (c+2)%3 == (c-1)%3 is safe.
        CP_WAIT(1);
        __syncthreads();

        const uint32_t aB = smem_base + (c % NSTAGE) * STG;
        const uint32_t bB = aB + A_ST;
#pragma unroll
        for (int ks = 0; ks < 4; ++ks) {
            uint32_t a[2][4], b[4][4];
#pragma unroll
            for (int i = 0; i < 2; i++)
                LDSM_X4(a[i][0], a[i][1], a[i][2], a[i][3],
                        aB + SWZ((a_row + i * 16) * 128 + ks * 32 + a_kb));
#pragma unroll
            for (int j = 0; j < 4; j++)
                LDSM_X4(b[j][0], b[j][1], b[j][2], b[j][3],
                        bB + SWZ((b_row + j * 16) * 128 + ks * 32 + b_kb));
#pragma unroll
            for (int i = 0; i < 2; i++)
#pragma unroll
                for (int j = 0; j < 4; j++) {
                    MMA16816F16(acc[i][2 * j + 0], a[i], b[j][0], b[j][1]);
                    MMA16816F16(acc[i][2 * j + 1], a[i], b[j][2], b[j][3]);
                }
        }

        if (c + 2 < NCHUNK) { prefetch(c + 2); CP_COMMIT(); }
    }

    const int m_base = mrow0 + wm * 32 + (lane >> 2);
    const int n_base = nrow0 + wn * 64 + (lane & 3) * 2;
#pragma unroll
    for (int i = 0; i < 2; i++) {
#pragma unroll
        for (int j = 0; j < 8; j++) {
            int n0 = n_base + j * 8;
            float b0 = bias[n0], b1 = bias[n0 + 1];
            int m0 = m_base + i * 16;
            float2 lo2 = {acc[i][j][0] + b0, acc[i][j][1] + b1};
            float2 hi2 = {acc[i][j][2] + b0, acc[i][j][3] + b1};
            *reinterpret_cast<float2*>(C + (size_t)m0 * N_DIM + n0)       = lo2;
            *reinterpret_cast<float2*>(C + (size_t)(m0 + 8) * N_DIM + n0) = hi2;
        }
    }
}

// -------- GroupNorm + SiLU + mult + SiLU, 2 rows per block ---------------
// warp w handles group w of rows 2*blk and 2*blk+1 with interleaved,
// independent dependency chains (2x ILP on loads, shuffles, MUFU).
__device__ __forceinline__ float fast_sigmoid(float x) {
    float e = __expf(-x);
    return __fdividef(1.0f, 1.0f + e);
}

__global__ __launch_bounds__(512)
void gn_silu_kernel(float* __restrict__ y,
                    const float* __restrict__ gn_w,
                    const float* __restrict__ gn_b,
                    const float* __restrict__ mult_w)
{
    const int row0 = blockIdx.x * 2;
    const int w    = threadIdx.x >> 5;
    const int lane = threadIdx.x & 31;

    float4* p0 = reinterpret_cast<float4*>(y + (size_t)row0 * N_DIM + w * GSIZE);
    float4* p1 = reinterpret_cast<float4*>(y + (size_t)(row0 + 1) * N_DIM + w * GSIZE);

    float4 v0[4], v1[4];
#pragma unroll
    for (int t = 0; t < 4; t++) { v0[t] = p0[lane + t * 32]; v1[t] = p1[lane + t * 32]; }

    float s0 = 0.0f, ss0 = 0.0f, s1 = 0.0f, ss1 = 0.0f;
#pragma unroll
    for (int t = 0; t < 4; t++) {
        s0  += v0[t].x + v0[t].y + v0[t].z + v0[t].w;
        ss0 += v0[t].x*v0[t].x + v0[t].y*v0[t].y + v0[t].z*v0[t].z + v0[t].w*v0[t].w;
        s1  += v1[t].x + v1[t].y + v1[t].z + v1[t].w;
        ss1 += v1[t].x*v1[t].x + v1[t].y*v1[t].y + v1[t].z*v1[t].z + v1[t].w*v1[t].w;
    }
#pragma unroll
    for (int o = 16; o > 0; o >>= 1) {
        s0  += __shfl_xor_sync(0xffffffffu, s0,  o);
        s1  += __shfl_xor_sync(0xffffffffu, s1,  o);
        ss0 += __shfl_xor_sync(0xffffffffu, ss0, o);
        ss1 += __shfl_xor_sync(0xffffffffu, ss1, o);
    }
    const float inv_n = 1.0f / (float)GSIZE;
    const float mean0 = s0 * inv_n;
    const float mean1 = s1 * inv_n;
    const float rstd0 = rsqrtf(fmaxf(ss0 * inv_n - mean0 * mean0, 0.0f) + EPS);
    const float rstd1 = rsqrtf(fmaxf(ss1 * inv_n - mean1 * mean1, 0.0f) + EPS);

#pragma unroll
    for (int t = 0; t < 4; t++) {
        float a0[4] = {v0[t].x, v0[t].y, v0[t].z, v0[t].w};
        float a1[4] = {v1[t].x, v1[t].y, v1[t].z, v1[t].w};
        float o0[4], o1[4];
        const int c0 = w * GSIZE + (lane + t * 32) * 4;
#pragma unroll
        for (int j = 0; j < 4; j++) {
            int c = c0 + j;
            float gw = gn_w[c], gb = gn_b[c], mw = mult_w[c];
            float n0 = (a0[j] - mean0) * rstd0 * gw + gb;
            float n1 = (a1[j] - mean1) * rstd1 * gw + gb;
            float t0 = n0 * fast_sigmoid(n0) * mw;
            float t1 = n1 * fast_sigmoid(n1) * mw;
            o0[j] = t0 * fast_sigmoid(t0);
            o1[j] = t1 * fast_sigmoid(t1);
        }
        float4 w0 = {o0[0], o0[1], o0[2], o0[3]};
        float4 w1 = {o1[0], o1[1], o1[2], o1[3]};
        p0[lane + t * 32] = w0;
        p1[lane + t * 32] = w1;
    }
}

// -------------------------------------------------------------------------
extern "C" void kernel_launch(void* const* d_in, const int* in_sizes, int n_in,
                              void* d_out, int out_size)
{
    const float* x      = (const float*)d_in[0];
    const float* W      = (const float*)d_in[1];
    const float* b      = (const float*)d_in[2];
    const float* gn_w   = (const float*)d_in[3];
    const float* gn_b   = (const float*)d_in[4];
    const float* mult_w = (const float*)d_in[5];
    float* out = (float*)d_out;

    __half *x16, *w16;
    cudaGetSymbolAddress((void**)&x16, g_x16);
    cudaGetSymbolAddress((void**)&w16, g_w16);

    int n8x   = (M_DIM * K_DIM) / 8;
    int n8tot = n8x + (N_DIM * K_DIM) / 8;
    cvt_both_kernel<<<(n8tot + 255) / 256, 256>>>(x, x16, W, w16, n8x, n8tot);

    cudaFuncSetAttribute(gemm_f16_kernel,
                         cudaFuncAttributeMaxDynamicSharedMemorySize, SMEM_GEMM);

    dim3 ggrid(M_DIM / BM, N_DIM / BN);   // (32, 64)
    gemm_f16_kernel<<<ggrid, 256, SMEM_GEMM>>>(b, out);

    gn_silu_kernel<<<M_DIM / 2, 512>>>(out, gn_w, gn_b, mult_w);
}